// round 5
// baseline (speedup 1.0000x reference)
#include <cuda_runtime.h>
#include <cuda_bf16.h>
#include <math.h>

// Problem constants
#define NN     8192
#define IN_F   256
#define OUT_F  128
#define ALPHA  0.2f

#define ADJ_WORDS_PER_ROW (NN / 32)   // 256
#define MAXDEG 128

// Scratch (device globals; no allocation)
__device__ unsigned g_adj[NN * ADJ_WORDS_PER_ROW];   // 8 MB bitmask (dedup + fallback)
__device__ int      g_deg[NN];                       // deduped degree
__device__ int      g_nbr[NN * MAXDEG];              // neighbor lists (4 MB)
__device__ float    g_Wh[NN * OUT_F];                // 4 MB
__device__ float    g_s1[NN];
__device__ float    g_s2[NN];

// ---------------------------------------------------------------------------
// Kernel 1: zero adjacency bitmask + degree array
// ---------------------------------------------------------------------------
__global__ __launch_bounds__(256) void zero_adj_kernel() {
    int idx = blockIdx.x * blockDim.x + threadIdx.x;      // uint4 index
    const int total = (NN * ADJ_WORDS_PER_ROW) / 4;       // 524288
    if (idx < total) {
        ((uint4*)g_adj)[idx] = make_uint4(0u, 0u, 0u, 0u);
    }
    if (idx < NN) g_deg[idx] = 0;
}

// ---------------------------------------------------------------------------
// Kernel 2: scatter edges; bitmask atomicOr dedups, unique edges appended.
// edge_index is int32.
// ---------------------------------------------------------------------------
__global__ __launch_bounds__(256) void scatter_kernel(const int* __restrict__ edge_index,
                                                      int E) {
    int k = blockIdx.x * blockDim.x + threadIdx.x;
    if (k < E) {
        int src = edge_index[k]     & (NN - 1);
        int dst = edge_index[E + k] & (NN - 1);
        unsigned bit = 1u << (dst & 31);
        unsigned old = atomicOr(&g_adj[src * ADJ_WORDS_PER_ROW + (dst >> 5)], bit);
        if (!(old & bit)) {
            int pos = atomicAdd(&g_deg[src], 1);
            if (pos < MAXDEG) g_nbr[src * MAXDEG + pos] = dst;
        }
    }
}

// ---------------------------------------------------------------------------
// Kernel 3: Wh = h @ W^T + b_lin (fused s1/s2 epilogue)  [R2 mainloop]
// ---------------------------------------------------------------------------
__global__ __launch_bounds__(256) void gemm_s_kernel(const float* __restrict__ h,
                                                     const float* __restrict__ W,
                                                     const float* __restrict__ b_lin,
                                                     const float* __restrict__ a) {
    const int BM = 64, BK = 32;
    __shared__ float hs[BK][BM];       // hs[k][m]
    __shared__ float ws[BK][OUT_F];    // ws[k][n]

    int row0 = blockIdx.x * BM;
    int tid  = threadIdx.x;
    int tr   = tid >> 5;   // warp id 0..7
    int tc   = tid & 31;   // lane

    float acc[8][4];
#pragma unroll
    for (int i = 0; i < 8; i++)
#pragma unroll
        for (int j = 0; j < 4; j++) acc[i][j] = 0.0f;

    for (int k0 = 0; k0 < IN_F; k0 += BK) {
#pragma unroll
        for (int l = 0; l < 2; l++) {
            int idx = tid + 256 * l;
            int m   = idx >> 3;
            int kq  = idx & 7;
            float4 v = *(const float4*)&h[(row0 + m) * IN_F + k0 + kq * 4];
            hs[kq * 4 + 0][m] = v.x;
            hs[kq * 4 + 1][m] = v.y;
            hs[kq * 4 + 2][m] = v.z;
            hs[kq * 4 + 3][m] = v.w;
        }
#pragma unroll
        for (int l = 0; l < 4; l++) {
            int idx = tid + 256 * l;
            int n   = idx >> 3;
            int kq  = idx & 7;
            float4 v = *(const float4*)&W[n * IN_F + k0 + kq * 4];
            ws[kq * 4 + 0][n] = v.x;
            ws[kq * 4 + 1][n] = v.y;
            ws[kq * 4 + 2][n] = v.z;
            ws[kq * 4 + 3][n] = v.w;
        }
        __syncthreads();

#pragma unroll
        for (int k = 0; k < BK; k++) {
            float4 ha = *(const float4*)&hs[k][tr * 8];
            float4 hb = *(const float4*)&hs[k][tr * 8 + 4];
            float4 wb = *(const float4*)&ws[k][tc * 4];
            float ra[8] = {ha.x, ha.y, ha.z, ha.w, hb.x, hb.y, hb.z, hb.w};
            float rb[4] = {wb.x, wb.y, wb.z, wb.w};
#pragma unroll
            for (int i = 0; i < 8; i++)
#pragma unroll
                for (int j = 0; j < 4; j++)
                    acc[i][j] = fmaf(ra[i], rb[j], acc[i][j]);
        }
        __syncthreads();
    }

    int col = tc * 4;
    float4 blv = *(const float4*)&b_lin[col];
    float4 a1v = *(const float4*)&a[col];
    float4 a2v = *(const float4*)&a[OUT_F + col];
    float bl[4]  = {blv.x, blv.y, blv.z, blv.w};
    float a1r[4] = {a1v.x, a1v.y, a1v.z, a1v.w};
    float a2r[4] = {a2v.x, a2v.y, a2v.z, a2v.w};

#pragma unroll
    for (int i = 0; i < 8; i++) {
        int row = row0 + tr * 8 + i;
        float v0 = acc[i][0] + bl[0];
        float v1 = acc[i][1] + bl[1];
        float v2 = acc[i][2] + bl[2];
        float v3 = acc[i][3] + bl[3];
        *(float4*)&g_Wh[row * OUT_F + col] = make_float4(v0, v1, v2, v3);
        float p1 = v0 * a1r[0] + v1 * a1r[1] + v2 * a1r[2] + v3 * a1r[3];
        float p2 = v0 * a2r[0] + v1 * a2r[1] + v2 * a2r[2] + v3 * a2r[3];
#pragma unroll
        for (int o = 16; o > 0; o >>= 1) {
            p1 += __shfl_xor_sync(0xffffffffu, p1, o);
            p2 += __shfl_xor_sync(0xffffffffu, p2, o);
        }
        if (tc == 0) {
            g_s1[row] = p1;
            g_s2[row] = p2;
        }
    }
}

// ---------------------------------------------------------------------------
// Kernel 4: warp-per-row softmax + aggregation + ELU.
// Block = 256 threads = 8 warps = 8 rows. No __syncthreads anywhere.
// Lane l owns features [4l, 4l+4): one float4 gather per neighbor per warp.
// ---------------------------------------------------------------------------
__device__ __forceinline__ float elu1(float v) {
    return (v > 0.0f) ? v : expm1f(v);
}

__global__ __launch_bounds__(256) void attn_kernel(const float* __restrict__ b_att_p,
                                                   float* __restrict__ out) {
    __shared__ int   sj[8][MAXDEG];
    __shared__ float sw[8][MAXDEG];

    const unsigned FULL = 0xffffffffu;
    int lane = threadIdx.x & 31;
    int wrp  = threadIdx.x >> 5;
    int i    = blockIdx.x * 8 + wrp;

    float batt = *b_att_p;
    float s1i  = g_s1[i];
    int   deg  = g_deg[i];
    int   col  = lane * 4;

    if (deg > 0 && deg <= MAXDEG) {
        // ---- fast path ----
        const int* nbr = &g_nbr[i * MAXDEG];

        int   jarr[4];
        float earr[4];
        float lmax = -INFINITY;
#pragma unroll
        for (int c = 0; c < 4; c++) {
            int k = c * 32 + lane;
            if (k < deg) {
                int j = nbr[k];
                float t = s1i + g_s2[j] + batt;
                float e = (t > 0.0f) ? t : ALPHA * t;
                jarr[c] = j;
                earr[c] = e;
                lmax = fmaxf(lmax, e);
            }
        }
#pragma unroll
        for (int o = 16; o > 0; o >>= 1)
            lmax = fmaxf(lmax, __shfl_xor_sync(FULL, lmax, o));

        float ls = 0.0f;
#pragma unroll
        for (int c = 0; c < 4; c++) {
            int k = c * 32 + lane;
            if (k < deg) {
                float w = __expf(earr[c] - lmax);
                sj[wrp][k] = jarr[c];
                sw[wrp][k] = w;
                ls += w;
            }
        }
#pragma unroll
        for (int o = 16; o > 0; o >>= 1)
            ls += __shfl_xor_sync(FULL, ls, o);
        __syncwarp();

        // aggregation: uniform smem reads broadcast (j, w) to the warp
        float4 acc = make_float4(0.f, 0.f, 0.f, 0.f);
        int k = 0;
        for (; k + 4 <= deg; k += 4) {
            int   j0 = sj[wrp][k],     j1 = sj[wrp][k + 1];
            int   j2 = sj[wrp][k + 2], j3 = sj[wrp][k + 3];
            float w0 = sw[wrp][k],     w1 = sw[wrp][k + 1];
            float w2 = sw[wrp][k + 2], w3 = sw[wrp][k + 3];
            float4 v0 = *(const float4*)&g_Wh[j0 * OUT_F + col];
            float4 v1 = *(const float4*)&g_Wh[j1 * OUT_F + col];
            float4 v2 = *(const float4*)&g_Wh[j2 * OUT_F + col];
            float4 v3 = *(const float4*)&g_Wh[j3 * OUT_F + col];
            acc.x = fmaf(w0, v0.x, acc.x); acc.y = fmaf(w0, v0.y, acc.y);
            acc.z = fmaf(w0, v0.z, acc.z); acc.w = fmaf(w0, v0.w, acc.w);
            acc.x = fmaf(w1, v1.x, acc.x); acc.y = fmaf(w1, v1.y, acc.y);
            acc.z = fmaf(w1, v1.z, acc.z); acc.w = fmaf(w1, v1.w, acc.w);
            acc.x = fmaf(w2, v2.x, acc.x); acc.y = fmaf(w2, v2.y, acc.y);
            acc.z = fmaf(w2, v2.z, acc.z); acc.w = fmaf(w2, v2.w, acc.w);
            acc.x = fmaf(w3, v3.x, acc.x); acc.y = fmaf(w3, v3.y, acc.y);
            acc.z = fmaf(w3, v3.z, acc.z); acc.w = fmaf(w3, v3.w, acc.w);
        }
        for (; k < deg; k++) {
            int   j = sj[wrp][k];
            float w = sw[wrp][k];
            float4 v = *(const float4*)&g_Wh[j * OUT_F + col];
            acc.x = fmaf(w, v.x, acc.x); acc.y = fmaf(w, v.y, acc.y);
            acc.z = fmaf(w, v.z, acc.z); acc.w = fmaf(w, v.w, acc.w);
        }

        float inv = 1.0f / ls;
        float4 r;
        r.x = elu1(acc.x * inv);
        r.y = elu1(acc.y * inv);
        r.z = elu1(acc.z * inv);
        r.w = elu1(acc.w * inv);
        *(float4*)&out[i * OUT_F + col] = r;
        return;
    }

    if (deg == 0) {
        // uniform softmax over all N (exactness fallback; never hit in practice)
        float4 acc = make_float4(0.f, 0.f, 0.f, 0.f);
        for (int j = 0; j < NN; j++) {
            float4 v = *(const float4*)&g_Wh[j * OUT_F + col];
            acc.x += v.x; acc.y += v.y; acc.z += v.z; acc.w += v.w;
        }
        const float inv = 1.0f / (float)NN;
        float4 r;
        r.x = elu1(acc.x * inv);
        r.y = elu1(acc.y * inv);
        r.z = elu1(acc.z * inv);
        r.w = elu1(acc.w * inv);
        *(float4*)&out[i * OUT_F + col] = r;
        return;
    }

    // ---- fallback: deg > MAXDEG, bitmask scan (safety net) ----
    const unsigned* adj = &g_adj[i * ADJ_WORDS_PER_ROW];

    float lmax = -INFINITY;
    for (int base = 0; base < NN; base += 32) {
        unsigned word = adj[base >> 5];
        if (word == 0u) continue;
        if ((word >> lane) & 1u) {
            int j = base + lane;
            float t = s1i + g_s2[j] + batt;
            float e = (t > 0.0f) ? t : ALPHA * t;
            lmax = fmaxf(lmax, e);
        }
    }
#pragma unroll
    for (int o = 16; o > 0; o >>= 1)
        lmax = fmaxf(lmax, __shfl_xor_sync(FULL, lmax, o));

    float4 acc = make_float4(0.f, 0.f, 0.f, 0.f);
    float sumw = 0.0f;
    for (int base = 0; base < NN; base += 32) {
        unsigned word = adj[base >> 5];
        unsigned bal  = __ballot_sync(FULL, word != 0u);  // keep warp converged
        if (word == 0u) continue;
        (void)bal;
        bool present = (word >> lane) & 1u;
        float wl = 0.0f;
        if (present) {
            int j = base + lane;
            float t = s1i + g_s2[j] + batt;
            float e = (t > 0.0f) ? t : ALPHA * t;
            wl = __expf(e - lmax);
            sumw += wl;
        }
        unsigned mask = word;
        while (mask) {
            int b = __ffs(mask) - 1;
            mask &= mask - 1;
            float w = __shfl_sync(FULL, wl, b);
            int j = base + b;
            float4 v = *(const float4*)&g_Wh[j * OUT_F + col];
            acc.x = fmaf(w, v.x, acc.x); acc.y = fmaf(w, v.y, acc.y);
            acc.z = fmaf(w, v.z, acc.z); acc.w = fmaf(w, v.w, acc.w);
        }
    }
#pragma unroll
    for (int o = 16; o > 0; o >>= 1)
        sumw += __shfl_xor_sync(FULL, sumw, o);

    float inv = 1.0f / sumw;
    float4 r;
    r.x = elu1(acc.x * inv);
    r.y = elu1(acc.y * inv);
    r.z = elu1(acc.z * inv);
    r.w = elu1(acc.w * inv);
    *(float4*)&out[i * OUT_F + col] = r;
}

// ---------------------------------------------------------------------------
// Launch
// Inputs: 0:h [N,256] f32, 1:edge_index [2,E] i32, 2:W [128,256] f32,
//         3:b_lin [128] f32, 4:a [1,256] f32, 5:b_att [1] f32
// ---------------------------------------------------------------------------
extern "C" void kernel_launch(void* const* d_in, const int* in_sizes, int n_in,
                              void* d_out, int out_size) {
    const float* h     = (const float*)d_in[0];
    const int*   ei    = (const int*)d_in[1];
    const float* W     = (const float*)d_in[2];
    const float* b_lin = (const float*)d_in[3];
    const float* a     = (const float*)d_in[4];
    const float* b_att = (const float*)d_in[5];
    float* out = (float*)d_out;

    int E = in_sizes[1] / 2;

    {
        int total = (NN * ADJ_WORDS_PER_ROW) / 4;
        zero_adj_kernel<<<(total + 255) / 256, 256>>>();
    }
    scatter_kernel<<<(E + 255) / 256, 256>>>(ei, E);
    gemm_s_kernel<<<NN / 64, 256>>>(h, W, b_lin, a);
    attn_kernel<<<NN / 8, 256>>>(b_att, out);
}